// round 15
// baseline (speedup 1.0000x reference)
#include <cuda_runtime.h>
#include <float.h>
#include <math.h>
#include <stdint.h>

// Problem constants
#define BB 4
#define NN 1024
#define DQ 256
#define HH 8
#define DD 32
#define MM (BB * NN)          // 4096 rows
#define KK 256                 // inner dim for all projections
#define QSCALE 0.17677669529663687f  // 32^-0.5
#define JSPLIT 2

// -------- scratch (no cudaMalloc allowed) --------
__device__ float g_q[BB * HH * NN * DD];     // [bh, n, d], pre-scaled
__device__ float g_k[BB * HH * NN * DD];
__device__ float g_v[BB * HH * NN * DD];
__device__ float g_gate[MM * DQ];            // sigmoid(x Wg^T + bg)
__device__ float g_t[MM * DQ];               // gated attention output
__device__ float g_po[JSPLIT][BB * HH * NN * DD];  // partial O (unnormalized)
__device__ float g_pl[JSPLIT][BB * HH * NN];       // partial l

// ---------------- helpers ----------------
__device__ __forceinline__ uint32_t f2tf32(float f) {
    uint32_t u;
    asm("cvt.rna.tf32.f32 %0, %1;" : "=r"(u) : "f"(f));
    return u;
}

__device__ __forceinline__ void mma_tf32(float d[4], const uint32_t a[4],
                                         uint32_t b0, uint32_t b1) {
    asm volatile(
        "mma.sync.aligned.m16n8k8.row.col.f32.tf32.tf32.f32 "
        "{%0,%1,%2,%3}, {%4,%5,%6,%7}, {%8,%9}, {%0,%1,%2,%3};\n"
        : "+f"(d[0]), "+f"(d[1]), "+f"(d[2]), "+f"(d[3])
        : "r"(a[0]), "r"(a[1]), "r"(a[2]), "r"(a[3]), "r"(b0), "r"(b1));
}

__device__ __forceinline__ void l2_prefetch(const void* p) {
    asm volatile("prefetch.global.L2 [%0];" :: "l"(p));
}

// ---------------- TF32 projection GEMM (unchanged from R13) ----------------
#define PSTRIDE 36

template <int KIND, int SETS>
__global__ __launch_bounds__(128, 4) void proj_kernel(
    const float* __restrict__ A_in,
    const float* __restrict__ Wq, const float* __restrict__ Wkv,
    const float* __restrict__ Wg, const float* __restrict__ bg,
    const float* __restrict__ bo, float* __restrict__ out)
{
    __shared__ float As[64 * SETS * PSTRIDE];
    __shared__ float Bs[64 * PSTRIDE];

    const int t    = threadIdx.x;
    const int warp = t >> 5;
    const int lane = t & 31;
    const int g    = lane >> 2;
    const int c4   = lane & 3;
    const int m0   = blockIdx.y * (64 * SETS);
    const int e0   = blockIdx.x * 64;

    const float* A;
    const float* Wt;
    if (KIND == 0) {
        A = A_in;
        if (e0 < 256)      Wt = Wq  + (size_t)e0 * KK;
        else if (e0 < 768) Wt = Wkv + (size_t)(e0 - 256) * KK;
        else               Wt = Wg  + (size_t)(e0 - 768) * KK;
    } else {
        A = (const float*)g_t;
        Wt = Wq + (size_t)e0 * KK;   // Wq slot carries Wo for KIND 1
    }

    float s[SETS][8][4];
#pragma unroll
    for (int st = 0; st < SETS; st++)
#pragma unroll
        for (int nt = 0; nt < 8; nt++)
            s[st][nt][0] = s[st][nt][1] = s[st][nt][2] = s[st][nt][3] = 0.f;

    const int row0 = warp * (16 * SETS) + g;

    for (int k0 = 0; k0 < KK; k0 += 32) {
        __syncthreads();
#pragma unroll
        for (int l = 0; l < 4 * SETS; l++) {
            int idx = t + (l << 7);
            int r   = idx >> 3;
            int c   = (idx & 7) << 2;
            float4 a4 = *(const float4*)(A + (size_t)(m0 + r) * KK + k0 + c);
            float4 ac;
            ac.x = __uint_as_float(f2tf32(a4.x));
            ac.y = __uint_as_float(f2tf32(a4.y));
            ac.z = __uint_as_float(f2tf32(a4.z));
            ac.w = __uint_as_float(f2tf32(a4.w));
            *(float4*)&As[r * PSTRIDE + c] = ac;
        }
#pragma unroll
        for (int l = 0; l < 4; l++) {
            int idx = t + (l << 7);
            int r   = idx >> 3;
            int c   = (idx & 7) << 2;
            float4 w4 = *(const float4*)(Wt + (size_t)r * KK + k0 + c);
            float4 wc;
            wc.x = __uint_as_float(f2tf32(w4.x));
            wc.y = __uint_as_float(f2tf32(w4.y));
            wc.z = __uint_as_float(f2tf32(w4.z));
            wc.w = __uint_as_float(f2tf32(w4.w));
            *(float4*)&Bs[r * PSTRIDE + c] = wc;
        }
        __syncthreads();

#pragma unroll
        for (int kk = 0; kk < 4; kk++) {
            uint32_t a[SETS][4];
#pragma unroll
            for (int st = 0; st < SETS; st++) {
                int rr = row0 + st * 16;
                a[st][0] = __float_as_uint(As[rr * PSTRIDE + kk * 8 + c4]);
                a[st][1] = __float_as_uint(As[(rr + 8) * PSTRIDE + kk * 8 + c4]);
                a[st][2] = __float_as_uint(As[rr * PSTRIDE + kk * 8 + c4 + 4]);
                a[st][3] = __float_as_uint(As[(rr + 8) * PSTRIDE + kk * 8 + c4 + 4]);
            }
#pragma unroll
            for (int nt = 0; nt < 8; nt++) {
                uint32_t b0 = __float_as_uint(Bs[(nt * 8 + g) * PSTRIDE + kk * 8 + c4]);
                uint32_t b1 = __float_as_uint(Bs[(nt * 8 + g) * PSTRIDE + kk * 8 + c4 + 4]);
#pragma unroll
                for (int st = 0; st < SETS; st++)
                    mma_tf32(s[st][nt], a[st], b0, b1);
            }
        }
    }

#pragma unroll
    for (int st = 0; st < SETS; st++) {
#pragma unroll
        for (int half = 0; half < 2; half++) {
            int m = m0 + row0 + st * 16 + half * 8;
            int b = m >> 10;
            int n = m & 1023;
#pragma unroll
            for (int nt = 0; nt < 8; nt++) {
                int e = e0 + nt * 8 + (c4 << 1);
                float v0 = half ? s[st][nt][2] : s[st][nt][0];
                float v1 = half ? s[st][nt][3] : s[st][nt][1];
                if (KIND == 1) {
                    float2 r;
                    r.x = v0 + bo[e];
                    r.y = v1 + bo[e + 1];
                    *(float2*)(out + (size_t)m * DQ + e) = r;
                } else if (e0 < 256) {
                    int h = e >> 5, d = e & 31;
                    float2 r; r.x = v0 * QSCALE; r.y = v1 * QSCALE;
                    *(float2*)(g_q + (((size_t)(b * HH + h) * NN + n) << 5) + d) = r;
                } else if (e0 < 512) {
                    int e2 = e - 256;
                    int h = e2 >> 5, d = e2 & 31;
                    float2 r; r.x = v0; r.y = v1;
                    *(float2*)(g_k + (((size_t)(b * HH + h) * NN + n) << 5) + d) = r;
                } else if (e0 < 768) {
                    int e2 = e - 512;
                    int h = e2 >> 5, d = e2 & 31;
                    float2 r; r.x = v0; r.y = v1;
                    *(float2*)(g_v + (((size_t)(b * HH + h) * NN + n) << 5) + d) = r;
                } else {
                    int e2 = e - 768;
                    float z0 = v0 + bg[e2];
                    float z1 = v1 + bg[e2 + 1];
                    float2 r;
                    r.x = 1.f / (1.f + __expf(-z0));
                    r.y = 1.f / (1.f + __expf(-z1));
                    *(float2*)(g_gate + (size_t)m * DQ + e2) = r;
                }
            }
        }
    }
}

// ---------------- attention: R13 inner loop, split over key range ----------------
// Block = 128 threads (4 warps), 128 query rows, HALF the key range; grid (8,32,2).
// Emits unnormalized partial O and partial l; combine kernel finishes.
#define K_STRIDE 36
#define V_STRIDE 40

__global__ __launch_bounds__(128, 4) void attn_mma_kernel(
    const float* __restrict__ bias, const float* __restrict__ mask)
{
    __shared__ float Ks[64 * K_STRIDE];
    __shared__ float Vs[64 * V_STRIDE];

    const int t    = threadIdx.x;
    const int warp = t >> 5;
    const int lane = t & 31;
    const int g    = lane >> 2;
    const int c4   = lane & 3;

    const int bh = blockIdx.y;
    const int b  = bh >> 3;
    const int sp = blockIdx.z;
    const int i0 = blockIdx.x * 128;
    const int row0 = i0 + warp * 32 + g;   // set st: rows row0+st*16, +8
    const int jbeg = sp * (NN / JSPLIT);
    const int jend = jbeg + (NN / JSPLIT);

    const float* qbase = g_q + ((size_t)(bh * NN) << 5);
    uint32_t qa[2][4][4];
#pragma unroll
    for (int st = 0; st < 2; st++) {
        int rr = row0 + st * 16;
#pragma unroll
        for (int kk = 0; kk < 4; kk++) {
            qa[st][kk][0] = f2tf32(qbase[((size_t)rr << 5) + kk * 8 + c4]);
            qa[st][kk][1] = f2tf32(qbase[((size_t)(rr + 8) << 5) + kk * 8 + c4]);
            qa[st][kk][2] = f2tf32(qbase[((size_t)rr << 5) + kk * 8 + c4 + 4]);
            qa[st][kk][3] = f2tf32(qbase[((size_t)(rr + 8) << 5) + kk * 8 + c4 + 4]);
        }
    }

    bool rv[2][2];
#pragma unroll
    for (int st = 0; st < 2; st++) {
        rv[st][0] = mask[b * NN + row0 + st * 16] > 0.f;
        rv[st][1] = mask[b * NN + row0 + st * 16 + 8] > 0.f;
    }

    const float* Kg = g_k + ((size_t)bh << 15);
    const float* Vg = g_v + ((size_t)bh << 15);
    const float* biasb = bias + ((size_t)(bh * NN + row0) << 10);
    const float* mrow  = mask + b * NN;

    float lacc[2][2];
    lacc[0][0] = lacc[0][1] = lacc[1][0] = lacc[1][1] = 0.f;
    float o[2][4][4];
#pragma unroll
    for (int st = 0; st < 2; st++)
#pragma unroll
        for (int nt = 0; nt < 4; nt++)
#pragma unroll
            for (int r = 0; r < 4; r++) o[st][nt][r] = 0.f;

    const int lA = (lane & 28) | (c4 >> 1);
    const int lB = lA | 2;
    const bool odd = (lane & 1);

    for (int j0 = jbeg; j0 < jend; j0 += 64) {
        __syncthreads();
        // cooperative K/V tile load, tf32 cvt at store
#pragma unroll
        for (int q = 0; q < 4; q++) {
            int id = t + (q << 7);
            int r  = id >> 3;
            int dc = (id & 7) << 2;
            float4 kf = *(const float4*)(Kg + ((size_t)(j0 + r) << 5) + dc);
            float4 vf = *(const float4*)(Vg + ((size_t)(j0 + r) << 5) + dc);
            float4 kc, vc;
            kc.x = __uint_as_float(f2tf32(kf.x));
            kc.y = __uint_as_float(f2tf32(kf.y));
            kc.z = __uint_as_float(f2tf32(kf.z));
            kc.w = __uint_as_float(f2tf32(kf.w));
            vc.x = __uint_as_float(f2tf32(vf.x));
            vc.y = __uint_as_float(f2tf32(vf.y));
            vc.z = __uint_as_float(f2tf32(vf.z));
            vc.w = __uint_as_float(f2tf32(vf.w));
            *(float4*)&Ks[r * K_STRIDE + dc] = kc;
            *(float4*)&Vs[r * V_STRIDE + dc] = vc;
        }
        __syncthreads();

        // L2 prefetch of next tile's bias rows
        if (j0 + 64 < jend) {
            const float* pb = biasb + (j0 + 64) + ((lane & 1) << 5);
#pragma unroll
            for (int st = 0; st < 2; st++) {
                l2_prefetch(pb + ((size_t)(st * 16) << 10));
                l2_prefetch(pb + ((size_t)(st * 16 + 8) << 10));
            }
        }

        // ---- S = Q K^T ----
        float s[2][8][4];
#pragma unroll
        for (int st = 0; st < 2; st++)
#pragma unroll
            for (int nt = 0; nt < 8; nt++)
                s[st][nt][0] = s[st][nt][1] = s[st][nt][2] = s[st][nt][3] = 0.f;
#pragma unroll
        for (int nt = 0; nt < 8; nt++) {
#pragma unroll
            for (int kk = 0; kk < 4; kk++) {
                uint32_t b0 = __float_as_uint(Ks[(nt * 8 + g) * K_STRIDE + kk * 8 + c4]);
                uint32_t b1 = __float_as_uint(Ks[(nt * 8 + g) * K_STRIDE + kk * 8 + c4 + 4]);
                mma_tf32(s[0][nt], qa[0][kk], b0, b1);
                mma_tf32(s[1][nt], qa[1][kk], b0, b1);
            }
        }

        // ---- bias + mask (branchless selects on exp INPUT) ----
#pragma unroll
        for (int nt = 0; nt < 8; nt++) {
            int jc = j0 + nt * 8 + (c4 << 1);
            float2 mk = *(const float2*)(mrow + jc);
            bool cx = mk.x > 0.f, cy = mk.y > 0.f;
#pragma unroll
            for (int st = 0; st < 2; st++) {
                float2 bz0 = *(const float2*)(biasb + ((size_t)(st * 16) << 10) + jc);
                float2 bz1 = *(const float2*)(biasb + ((size_t)(st * 16 + 8) << 10) + jc);
                s[st][nt][0] = (rv[st][0] && cx) ? s[st][nt][0] + bz0.x : -1e30f;
                s[st][nt][1] = (rv[st][0] && cy) ? s[st][nt][1] + bz0.y : -1e30f;
                s[st][nt][2] = (rv[st][1] && cx) ? s[st][nt][2] + bz1.x : -1e30f;
                s[st][nt][3] = (rv[st][1] && cy) ? s[st][nt][3] + bz1.y : -1e30f;
            }
        }

        // ---- p = exp(s), unconditional; lane-local l ----
#pragma unroll
        for (int st = 0; st < 2; st++) {
#pragma unroll
            for (int nt = 0; nt < 8; nt++) {
                float p0 = __expf(s[st][nt][0]);
                float p1 = __expf(s[st][nt][1]);
                float p2 = __expf(s[st][nt][2]);
                float p3 = __expf(s[st][nt][3]);
                lacc[st][0] += p0 + p1;
                lacc[st][1] += p2 + p3;
                s[st][nt][0] = __uint_as_float(f2tf32(p0));
                s[st][nt][1] = __uint_as_float(f2tf32(p1));
                s[st][nt][2] = __uint_as_float(f2tf32(p2));
                s[st][nt][3] = __uint_as_float(f2tf32(p3));
            }
        }

        // ---- O += P V ----
#pragma unroll
        for (int kk = 0; kk < 8; kk++) {
            uint32_t a[2][4];
#pragma unroll
            for (int st = 0; st < 2; st++) {
#pragma unroll
                for (int hv = 0; hv < 2; hv++) {
                    int src = hv ? lB : lA;
                    float w0 = __shfl_sync(0xffffffffu, s[st][kk][0], src);
                    float w1 = __shfl_sync(0xffffffffu, s[st][kk][1], src);
                    float w2 = __shfl_sync(0xffffffffu, s[st][kk][2], src);
                    float w3 = __shfl_sync(0xffffffffu, s[st][kk][3], src);
                    a[st][hv * 2 + 0] = __float_as_uint(odd ? w1 : w0);
                    a[st][hv * 2 + 1] = __float_as_uint(odd ? w3 : w2);
                }
            }
#pragma unroll
            for (int nt = 0; nt < 4; nt++) {
                uint32_t b0 = __float_as_uint(Vs[(kk * 8 + c4) * V_STRIDE + nt * 8 + g]);
                uint32_t b1 = __float_as_uint(Vs[(kk * 8 + c4 + 4) * V_STRIDE + nt * 8 + g]);
                mma_tf32(o[0][nt], a[0], b0, b1);
                mma_tf32(o[1][nt], a[1], b0, b1);
            }
        }
    }

    // ---- epilogue: write partial O and partial l ----
    float* po = g_po[sp];
    float* pl = g_pl[sp];
#pragma unroll
    for (int st = 0; st < 2; st++) {
        float l0 = lacc[st][0], l1 = lacc[st][1];
        l0 += __shfl_xor_sync(0xffffffffu, l0, 1);
        l0 += __shfl_xor_sync(0xffffffffu, l0, 2);
        l1 += __shfl_xor_sync(0xffffffffu, l1, 1);
        l1 += __shfl_xor_sync(0xffffffffu, l1, 2);
        int r0 = row0 + st * 16;
        if (c4 == 0) {
            pl[bh * NN + r0] = l0;
            pl[bh * NN + r0 + 8] = l1;
        }
        size_t po0 = ((size_t)(bh * NN + r0) << 5);
        size_t po1 = ((size_t)(bh * NN + r0 + 8) << 5);
#pragma unroll
        for (int nt = 0; nt < 4; nt++) {
            int dc = nt * 8 + (c4 << 1);
            float2 w0, w1;
            w0.x = o[st][nt][0]; w0.y = o[st][nt][1];
            w1.x = o[st][nt][2]; w1.y = o[st][nt][3];
            *(float2*)(po + po0 + dc) = w0;
            *(float2*)(po + po1 + dc) = w1;
        }
    }
}

// ---------------- combine: O = (sum O_p) / (sum l_p) * gate -> g_t ----------------
__global__ __launch_bounds__(256) void combine_kernel()
{
    int idx = blockIdx.x * 256 + threadIdx.x;   // over BB*HH*NN*16 float2
    int bhn = idx >> 4;
    int d   = (idx & 15) << 1;
    int bh  = bhn >> 10;
    int n   = bhn & 1023;
    int m   = (bh >> 3) * NN + n;
    int e   = ((bh & 7) << 5) + d;

    size_t fo = ((size_t)idx) << 1;
    float2 a = *(const float2*)(g_po[0] + fo);
    float2 c = *(const float2*)(g_po[1] + fo);
    float inv = 1.f / (g_pl[0][bhn] + g_pl[1][bhn]);
    float2 gt = *(const float2*)(g_gate + (size_t)m * DQ + e);
    float2 r;
    r.x = (a.x + c.x) * inv * gt.x;
    r.y = (a.y + c.y) * inv * gt.y;
    *(float2*)(g_t + (size_t)m * DQ + e) = r;
}

extern "C" void kernel_launch(void* const* d_in, const int* in_sizes, int n_in,
                              void* d_out, int out_size)
{
    const float* x    = (const float*)d_in[0];
    const float* mask = (const float*)d_in[1];
    const float* bias = (const float*)d_in[2];
    const float* Wq   = (const float*)d_in[3];
    const float* Wkv  = (const float*)d_in[4];
    const float* Wo   = (const float*)d_in[5];
    const float* bo   = (const float*)d_in[6];
    const float* Wg   = (const float*)d_in[7];
    const float* bg   = (const float*)d_in[8];
    float* out = (float*)d_out;

    dim3 blk(128);
    // Fused Q + KV + Gate projections (virtual E = 1024), m-tile 128
    proj_kernel<0, 2><<<dim3(16, 32), blk>>>(x, Wq, Wkv, Wg, bg, nullptr, nullptr);
    // Attention: split over key range -> 512 blocks for latency hiding
    attn_mma_kernel<<<dim3(NN / 128, BB * HH, JSPLIT), blk>>>(bias, mask);
    // Combine partials + gate
    combine_kernel<<<dim3(BB * HH * NN * 16 / 256), dim3(256)>>>();
    // Output projection (A = g_t, W = Wo in the Wq slot), m-tile 64
    proj_kernel<1, 1><<<dim3(4, 64), blk>>>(nullptr, Wo, nullptr, nullptr, nullptr, bo, out);
}

// round 16
// speedup vs baseline: 1.1388x; 1.1388x over previous
#include <cuda_runtime.h>
#include <float.h>
#include <math.h>
#include <stdint.h>

// Problem constants
#define BB 4
#define NN 1024
#define DQ 256
#define HH 8
#define DD 32
#define MM (BB * NN)          // 4096 rows
#define KK 256                 // inner dim for all projections
#define QSCALE 0.17677669529663687f  // 32^-0.5

// -------- scratch (no cudaMalloc allowed) --------
__device__ float g_q[BB * HH * NN * DD];     // [bh, n, d], pre-scaled
__device__ float g_k[BB * HH * NN * DD];
__device__ float g_v[BB * HH * NN * DD];
__device__ float g_gate[MM * DQ];            // sigmoid(x Wg^T + bg)
__device__ float g_t[MM * DQ];               // gated attention output
__device__ float g_po[2][MM * DQ];           // output-proj partials

// ---------------- helpers ----------------
__device__ __forceinline__ uint32_t f2tf32(float f) {
    uint32_t u;
    asm("cvt.rna.tf32.f32 %0, %1;" : "=r"(u) : "f"(f));
    return u;
}

__device__ __forceinline__ void mma_tf32(float d[4], const uint32_t a[4],
                                         uint32_t b0, uint32_t b1) {
    asm volatile(
        "mma.sync.aligned.m16n8k8.row.col.f32.tf32.tf32.f32 "
        "{%0,%1,%2,%3}, {%4,%5,%6,%7}, {%8,%9}, {%0,%1,%2,%3};\n"
        : "+f"(d[0]), "+f"(d[1]), "+f"(d[2]), "+f"(d[3])
        : "r"(a[0]), "r"(a[1]), "r"(a[2]), "r"(a[3]), "r"(b0), "r"(b1));
}

__device__ __forceinline__ void l2_prefetch(const void* p) {
    asm volatile("prefetch.global.L2 [%0];" :: "l"(p));
}

// ---------------- TF32 projection GEMM ----------------
// KIND 0: fused QKV+Gate (virtual E=1024), full K.
// KIND 2: output projection partial: A = g_t, K-half per blockIdx.z -> g_po[z].
#define PSTRIDE 36

template <int KIND, int SETS>
__global__ __launch_bounds__(128, 4) void proj_kernel(
    const float* __restrict__ A_in,
    const float* __restrict__ Wq, const float* __restrict__ Wkv,
    const float* __restrict__ Wg, const float* __restrict__ bg,
    const float* __restrict__ bo, float* __restrict__ out)
{
    __shared__ float As[64 * SETS * PSTRIDE];
    __shared__ float Bs[64 * PSTRIDE];

    const int t    = threadIdx.x;
    const int warp = t >> 5;
    const int lane = t & 31;
    const int g    = lane >> 2;
    const int c4   = lane & 3;
    const int m0   = blockIdx.y * (64 * SETS);
    const int e0   = blockIdx.x * 64;

    const float* A;
    const float* Wt;
    int kbeg, kend;
    if (KIND == 0) {
        A = A_in;
        if (e0 < 256)      Wt = Wq  + (size_t)e0 * KK;
        else if (e0 < 768) Wt = Wkv + (size_t)(e0 - 256) * KK;
        else               Wt = Wg  + (size_t)(e0 - 768) * KK;
        kbeg = 0; kend = KK;
    } else {
        A = (const float*)g_t;
        Wt = Wq + (size_t)e0 * KK;   // Wq slot carries Wo
        kbeg = blockIdx.z * (KK / 2);
        kend = kbeg + (KK / 2);
    }

    float s[SETS][8][4];
#pragma unroll
    for (int st = 0; st < SETS; st++)
#pragma unroll
        for (int nt = 0; nt < 8; nt++)
            s[st][nt][0] = s[st][nt][1] = s[st][nt][2] = s[st][nt][3] = 0.f;

    const int row0 = warp * (16 * SETS) + g;

    for (int k0 = kbeg; k0 < kend; k0 += 32) {
        __syncthreads();
#pragma unroll
        for (int l = 0; l < 4 * SETS; l++) {
            int idx = t + (l << 7);
            int r   = idx >> 3;
            int c   = (idx & 7) << 2;
            float4 a4 = *(const float4*)(A + (size_t)(m0 + r) * KK + k0 + c);
            float4 ac;
            ac.x = __uint_as_float(f2tf32(a4.x));
            ac.y = __uint_as_float(f2tf32(a4.y));
            ac.z = __uint_as_float(f2tf32(a4.z));
            ac.w = __uint_as_float(f2tf32(a4.w));
            *(float4*)&As[r * PSTRIDE + c] = ac;
        }
#pragma unroll
        for (int l = 0; l < 4; l++) {
            int idx = t + (l << 7);
            int r   = idx >> 3;
            int c   = (idx & 7) << 2;
            float4 w4 = *(const float4*)(Wt + (size_t)r * KK + k0 + c);
            float4 wc;
            wc.x = __uint_as_float(f2tf32(w4.x));
            wc.y = __uint_as_float(f2tf32(w4.y));
            wc.z = __uint_as_float(f2tf32(w4.z));
            wc.w = __uint_as_float(f2tf32(w4.w));
            *(float4*)&Bs[r * PSTRIDE + c] = wc;
        }
        __syncthreads();

#pragma unroll
        for (int kk = 0; kk < 4; kk++) {
            uint32_t a[SETS][4];
#pragma unroll
            for (int st = 0; st < SETS; st++) {
                int rr = row0 + st * 16;
                a[st][0] = __float_as_uint(As[rr * PSTRIDE + kk * 8 + c4]);
                a[st][1] = __float_as_uint(As[(rr + 8) * PSTRIDE + kk * 8 + c4]);
                a[st][2] = __float_as_uint(As[rr * PSTRIDE + kk * 8 + c4 + 4]);
                a[st][3] = __float_as_uint(As[(rr + 8) * PSTRIDE + kk * 8 + c4 + 4]);
            }
#pragma unroll
            for (int nt = 0; nt < 8; nt++) {
                uint32_t b0 = __float_as_uint(Bs[(nt * 8 + g) * PSTRIDE + kk * 8 + c4]);
                uint32_t b1 = __float_as_uint(Bs[(nt * 8 + g) * PSTRIDE + kk * 8 + c4 + 4]);
#pragma unroll
                for (int st = 0; st < SETS; st++)
                    mma_tf32(s[st][nt], a[st], b0, b1);
            }
        }
    }

#pragma unroll
    for (int st = 0; st < SETS; st++) {
#pragma unroll
        for (int half = 0; half < 2; half++) {
            int m = m0 + row0 + st * 16 + half * 8;
            int b = m >> 10;
            int n = m & 1023;
#pragma unroll
            for (int nt = 0; nt < 8; nt++) {
                int e = e0 + nt * 8 + (c4 << 1);
                float v0 = half ? s[st][nt][2] : s[st][nt][0];
                float v1 = half ? s[st][nt][3] : s[st][nt][1];
                if (KIND == 2) {
                    float2 r; r.x = v0; r.y = v1;
                    *(float2*)(g_po[blockIdx.z] + (size_t)m * DQ + e) = r;
                } else if (e0 < 256) {
                    int h = e >> 5, d = e & 31;
                    float2 r; r.x = v0 * QSCALE; r.y = v1 * QSCALE;
                    *(float2*)(g_q + (((size_t)(b * HH + h) * NN + n) << 5) + d) = r;
                } else if (e0 < 512) {
                    int e2 = e - 256;
                    int h = e2 >> 5, d = e2 & 31;
                    float2 r; r.x = v0; r.y = v1;
                    *(float2*)(g_k + (((size_t)(b * HH + h) * NN + n) << 5) + d) = r;
                } else if (e0 < 768) {
                    int e2 = e - 512;
                    int h = e2 >> 5, d = e2 & 31;
                    float2 r; r.x = v0; r.y = v1;
                    *(float2*)(g_v + (((size_t)(b * HH + h) * NN + n) << 5) + d) = r;
                } else {
                    int e2 = e - 768;
                    float z0 = v0 + bg[e2];
                    float z1 = v1 + bg[e2 + 1];
                    float2 r;
                    r.x = 1.f / (1.f + __expf(-z0));
                    r.y = 1.f / (1.f + __expf(-z1));
                    *(float2*)(g_gate + (size_t)m * DQ + e2) = r;
                }
            }
        }
    }
}

// ---------------- combine output-proj partials + bias ----------------
__global__ __launch_bounds__(256) void combine2_kernel(
    const float* __restrict__ bo, float* __restrict__ out)
{
    int idx = blockIdx.x * 256 + threadIdx.x;   // over MM*DQ/2 float2
    int e = (idx << 1) & (DQ - 1);
    size_t fo = ((size_t)idx) << 1;
    float2 a = *(const float2*)(g_po[0] + fo);
    float2 c = *(const float2*)(g_po[1] + fo);
    float2 r;
    r.x = a.x + c.x + bo[e];
    r.y = a.y + c.y + bo[e + 1];
    *(float2*)(out + fo) = r;
}

// ---------------- attention: R13 (best) — byte-identical ----------------
#define K_STRIDE 36
#define V_STRIDE 40

__global__ __launch_bounds__(128, 2) void attn_mma_kernel(
    const float* __restrict__ bias, const float* __restrict__ mask)
{
    __shared__ float Ks[64 * K_STRIDE];
    __shared__ float Vs[64 * V_STRIDE];

    const int t    = threadIdx.x;
    const int warp = t >> 5;
    const int lane = t & 31;
    const int g    = lane >> 2;
    const int c4   = lane & 3;

    const int bh = blockIdx.y;
    const int b  = bh >> 3;
    const int h  = bh & 7;
    const int i0 = blockIdx.x * 128;
    const int row0 = i0 + warp * 32 + g;   // set st: rows row0+st*16, +8

    const float* qbase = g_q + ((size_t)(bh * NN) << 5);
    uint32_t qa[2][4][4];
#pragma unroll
    for (int st = 0; st < 2; st++) {
        int rr = row0 + st * 16;
#pragma unroll
        for (int kk = 0; kk < 4; kk++) {
            qa[st][kk][0] = f2tf32(qbase[((size_t)rr << 5) + kk * 8 + c4]);
            qa[st][kk][1] = f2tf32(qbase[((size_t)(rr + 8) << 5) + kk * 8 + c4]);
            qa[st][kk][2] = f2tf32(qbase[((size_t)rr << 5) + kk * 8 + c4 + 4]);
            qa[st][kk][3] = f2tf32(qbase[((size_t)(rr + 8) << 5) + kk * 8 + c4 + 4]);
        }
    }

    bool rv[2][2];
#pragma unroll
    for (int st = 0; st < 2; st++) {
        rv[st][0] = mask[b * NN + row0 + st * 16] > 0.f;
        rv[st][1] = mask[b * NN + row0 + st * 16 + 8] > 0.f;
    }

    const float* Kg = g_k + ((size_t)bh << 15);
    const float* Vg = g_v + ((size_t)bh << 15);
    const float* biasb = bias + ((size_t)(bh * NN + row0) << 10);
    const float* mrow  = mask + b * NN;

    float lacc[2][2];
    lacc[0][0] = lacc[0][1] = lacc[1][0] = lacc[1][1] = 0.f;
    float o[2][4][4];
#pragma unroll
    for (int st = 0; st < 2; st++)
#pragma unroll
        for (int nt = 0; nt < 4; nt++)
#pragma unroll
            for (int r = 0; r < 4; r++) o[st][nt][r] = 0.f;

    const int lA = (lane & 28) | (c4 >> 1);
    const int lB = lA | 2;
    const bool odd = (lane & 1);

    for (int j0 = 0; j0 < NN; j0 += 64) {
        __syncthreads();
#pragma unroll
        for (int q = 0; q < 4; q++) {
            int id = t + (q << 7);
            int r  = id >> 3;
            int dc = (id & 7) << 2;
            float4 kf = *(const float4*)(Kg + ((size_t)(j0 + r) << 5) + dc);
            float4 vf = *(const float4*)(Vg + ((size_t)(j0 + r) << 5) + dc);
            float4 kc, vc;
            kc.x = __uint_as_float(f2tf32(kf.x));
            kc.y = __uint_as_float(f2tf32(kf.y));
            kc.z = __uint_as_float(f2tf32(kf.z));
            kc.w = __uint_as_float(f2tf32(kf.w));
            vc.x = __uint_as_float(f2tf32(vf.x));
            vc.y = __uint_as_float(f2tf32(vf.y));
            vc.z = __uint_as_float(f2tf32(vf.z));
            vc.w = __uint_as_float(f2tf32(vf.w));
            *(float4*)&Ks[r * K_STRIDE + dc] = kc;
            *(float4*)&Vs[r * V_STRIDE + dc] = vc;
        }
        __syncthreads();

        // L2 prefetch of next tile's bias rows
        if (j0 + 64 < NN) {
            const float* pb = biasb + (j0 + 64) + ((lane & 1) << 5);
#pragma unroll
            for (int st = 0; st < 2; st++) {
                l2_prefetch(pb + ((size_t)(st * 16) << 10));
                l2_prefetch(pb + ((size_t)(st * 16 + 8) << 10));
            }
        }

        // ---- S = Q K^T ----
        float s[2][8][4];
#pragma unroll
        for (int st = 0; st < 2; st++)
#pragma unroll
            for (int nt = 0; nt < 8; nt++)
                s[st][nt][0] = s[st][nt][1] = s[st][nt][2] = s[st][nt][3] = 0.f;
#pragma unroll
        for (int nt = 0; nt < 8; nt++) {
#pragma unroll
            for (int kk = 0; kk < 4; kk++) {
                uint32_t b0 = __float_as_uint(Ks[(nt * 8 + g) * K_STRIDE + kk * 8 + c4]);
                uint32_t b1 = __float_as_uint(Ks[(nt * 8 + g) * K_STRIDE + kk * 8 + c4 + 4]);
                mma_tf32(s[0][nt], qa[0][kk], b0, b1);
                mma_tf32(s[1][nt], qa[1][kk], b0, b1);
            }
        }

        // ---- bias + mask (branchless selects on exp INPUT) ----
#pragma unroll
        for (int nt = 0; nt < 8; nt++) {
            int jc = j0 + nt * 8 + (c4 << 1);
            float2 mk = *(const float2*)(mrow + jc);
            bool cx = mk.x > 0.f, cy = mk.y > 0.f;
#pragma unroll
            for (int st = 0; st < 2; st++) {
                float2 bz0 = *(const float2*)(biasb + ((size_t)(st * 16) << 10) + jc);
                float2 bz1 = *(const float2*)(biasb + ((size_t)(st * 16 + 8) << 10) + jc);
                s[st][nt][0] = (rv[st][0] && cx) ? s[st][nt][0] + bz0.x : -1e30f;
                s[st][nt][1] = (rv[st][0] && cy) ? s[st][nt][1] + bz0.y : -1e30f;
                s[st][nt][2] = (rv[st][1] && cx) ? s[st][nt][2] + bz1.x : -1e30f;
                s[st][nt][3] = (rv[st][1] && cy) ? s[st][nt][3] + bz1.y : -1e30f;
            }
        }

        // ---- p = exp(s), unconditional; lane-local l ----
#pragma unroll
        for (int st = 0; st < 2; st++) {
#pragma unroll
            for (int nt = 0; nt < 8; nt++) {
                float p0 = __expf(s[st][nt][0]);
                float p1 = __expf(s[st][nt][1]);
                float p2 = __expf(s[st][nt][2]);
                float p3 = __expf(s[st][nt][3]);
                lacc[st][0] += p0 + p1;
                lacc[st][1] += p2 + p3;
                s[st][nt][0] = __uint_as_float(f2tf32(p0));
                s[st][nt][1] = __uint_as_float(f2tf32(p1));
                s[st][nt][2] = __uint_as_float(f2tf32(p2));
                s[st][nt][3] = __uint_as_float(f2tf32(p3));
            }
        }

        // ---- O += P V ----
#pragma unroll
        for (int kk = 0; kk < 8; kk++) {
            uint32_t a[2][4];
#pragma unroll
            for (int st = 0; st < 2; st++) {
#pragma unroll
                for (int hv = 0; hv < 2; hv++) {
                    int src = hv ? lB : lA;
                    float w0 = __shfl_sync(0xffffffffu, s[st][kk][0], src);
                    float w1 = __shfl_sync(0xffffffffu, s[st][kk][1], src);
                    float w2 = __shfl_sync(0xffffffffu, s[st][kk][2], src);
                    float w3 = __shfl_sync(0xffffffffu, s[st][kk][3], src);
                    a[st][hv * 2 + 0] = __float_as_uint(odd ? w1 : w0);
                    a[st][hv * 2 + 1] = __float_as_uint(odd ? w3 : w2);
                }
            }
#pragma unroll
            for (int nt = 0; nt < 4; nt++) {
                uint32_t b0 = __float_as_uint(Vs[(kk * 8 + c4) * V_STRIDE + nt * 8 + g]);
                uint32_t b1 = __float_as_uint(Vs[(kk * 8 + c4 + 4) * V_STRIDE + nt * 8 + g]);
                mma_tf32(o[0][nt], a[0], b0, b1);
                mma_tf32(o[1][nt], a[1], b0, b1);
            }
        }
    }

    // ---- single cross-lane l reduction + epilogue ----
#pragma unroll
    for (int st = 0; st < 2; st++) {
        float l0 = lacc[st][0], l1 = lacc[st][1];
        l0 += __shfl_xor_sync(0xffffffffu, l0, 1);
        l0 += __shfl_xor_sync(0xffffffffu, l0, 2);
        l1 += __shfl_xor_sync(0xffffffffu, l1, 1);
        l1 += __shfl_xor_sync(0xffffffffu, l1, 2);
        float inv0 = 1.f / l0, inv1 = 1.f / l1;
        size_t mr0 = (size_t)(b * NN + row0 + st * 16) * DQ + h * 32;
        size_t mr1 = mr0 + (size_t)8 * DQ;
#pragma unroll
        for (int nt = 0; nt < 4; nt++) {
            int dc = nt * 8 + (c4 << 1);
            float2 gt0 = *(const float2*)(g_gate + mr0 + dc);
            float2 gt1 = *(const float2*)(g_gate + mr1 + dc);
            float2 r0, r1;
            r0.x = o[st][nt][0] * inv0 * gt0.x;
            r0.y = o[st][nt][1] * inv0 * gt0.y;
            r1.x = o[st][nt][2] * inv1 * gt1.x;
            r1.y = o[st][nt][3] * inv1 * gt1.y;
            *(float2*)(g_t + mr0 + dc) = r0;
            *(float2*)(g_t + mr1 + dc) = r1;
        }
    }
}

extern "C" void kernel_launch(void* const* d_in, const int* in_sizes, int n_in,
                              void* d_out, int out_size)
{
    const float* x    = (const float*)d_in[0];
    const float* mask = (const float*)d_in[1];
    const float* bias = (const float*)d_in[2];
    const float* Wq   = (const float*)d_in[3];
    const float* Wkv  = (const float*)d_in[4];
    const float* Wo   = (const float*)d_in[5];
    const float* bo   = (const float*)d_in[6];
    const float* Wg   = (const float*)d_in[7];
    const float* bg   = (const float*)d_in[8];
    float* out = (float*)d_out;

    dim3 blk(128);
    // Fused Q + KV + Gate projections (virtual E = 1024), m-tile 128
    proj_kernel<0, 2><<<dim3(16, 32), blk>>>(x, Wq, Wkv, Wg, bg, nullptr, nullptr);
    // Attention (+ gating): R13 best config
    attn_mma_kernel<<<dim3(NN / 128, BB * HH), blk>>>(bias, mask);
    // Output projection: K-split into 2 partials (grid 512) + combine
    proj_kernel<2, 1><<<dim3(4, 64, 2), blk>>>(nullptr, Wo, nullptr, nullptr, nullptr, nullptr, nullptr);
    combine2_kernel<<<dim3(MM * DQ / 2 / 256), dim3(256)>>>(bo, out);
}

// round 17
// speedup vs baseline: 1.1518x; 1.0114x over previous
#include <cuda_runtime.h>
#include <float.h>
#include <math.h>
#include <stdint.h>

// Problem constants
#define BB 4
#define NN 1024
#define DQ 256
#define HH 8
#define DD 32
#define MM (BB * NN)          // 4096 rows
#define KK 256                 // inner dim for all projections
#define QSCALE 0.17677669529663687f  // 32^-0.5

// -------- scratch (no cudaMalloc allowed) --------
__device__ float g_q[BB * HH * NN * DD];     // [bh, n, d], pre-scaled
__device__ float g_k[BB * HH * NN * DD];
__device__ float g_v[BB * HH * NN * DD];
__device__ float g_gate[MM * DQ];            // sigmoid(x Wg^T + bg)
__device__ float g_t[MM * DQ];               // gated attention output

// ---------------- helpers ----------------
__device__ __forceinline__ uint32_t f2tf32(float f) {
    uint32_t u;
    asm("cvt.rna.tf32.f32 %0, %1;" : "=r"(u) : "f"(f));
    return u;
}

__device__ __forceinline__ void mma_tf32(float d[4], const uint32_t a[4],
                                         uint32_t b0, uint32_t b1) {
    asm volatile(
        "mma.sync.aligned.m16n8k8.row.col.f32.tf32.tf32.f32 "
        "{%0,%1,%2,%3}, {%4,%5,%6,%7}, {%8,%9}, {%0,%1,%2,%3};\n"
        : "+f"(d[0]), "+f"(d[1]), "+f"(d[2]), "+f"(d[3])
        : "r"(a[0]), "r"(a[1]), "r"(a[2]), "r"(a[3]), "r"(b0), "r"(b1));
}

__device__ __forceinline__ void l2_prefetch(const void* p) {
    asm volatile("prefetch.global.L2 [%0];" :: "l"(p));
}

// ---------------- TF32 projection GEMM (R13 form) ----------------
#define PSTRIDE 36

template <int KIND, int SETS>
__global__ __launch_bounds__(128, 4) void proj_kernel(
    const float* __restrict__ A_in,
    const float* __restrict__ Wq, const float* __restrict__ Wkv,
    const float* __restrict__ Wg, const float* __restrict__ bg,
    const float* __restrict__ bo, float* __restrict__ out)
{
    __shared__ float As[64 * SETS * PSTRIDE];
    __shared__ float Bs[64 * PSTRIDE];

    const int t    = threadIdx.x;
    const int warp = t >> 5;
    const int lane = t & 31;
    const int g    = lane >> 2;
    const int c4   = lane & 3;
    const int m0   = blockIdx.y * (64 * SETS);
    const int e0   = blockIdx.x * 64;

    const float* A;
    const float* Wt;
    if (KIND == 0) {
        A = A_in;
        if (e0 < 256)      Wt = Wq  + (size_t)e0 * KK;
        else if (e0 < 768) Wt = Wkv + (size_t)(e0 - 256) * KK;
        else               Wt = Wg  + (size_t)(e0 - 768) * KK;
    } else {
        A = (const float*)g_t;
        Wt = Wq + (size_t)e0 * KK;   // Wq slot carries Wo for KIND 1
    }

    float s[SETS][8][4];
#pragma unroll
    for (int st = 0; st < SETS; st++)
#pragma unroll
        for (int nt = 0; nt < 8; nt++)
            s[st][nt][0] = s[st][nt][1] = s[st][nt][2] = s[st][nt][3] = 0.f;

    const int row0 = warp * (16 * SETS) + g;

    for (int k0 = 0; k0 < KK; k0 += 32) {
        __syncthreads();
#pragma unroll
        for (int l = 0; l < 4 * SETS; l++) {
            int idx = t + (l << 7);
            int r   = idx >> 3;
            int c   = (idx & 7) << 2;
            float4 a4 = *(const float4*)(A + (size_t)(m0 + r) * KK + k0 + c);
            float4 ac;
            ac.x = __uint_as_float(f2tf32(a4.x));
            ac.y = __uint_as_float(f2tf32(a4.y));
            ac.z = __uint_as_float(f2tf32(a4.z));
            ac.w = __uint_as_float(f2tf32(a4.w));
            *(float4*)&As[r * PSTRIDE + c] = ac;
        }
#pragma unroll
        for (int l = 0; l < 4; l++) {
            int idx = t + (l << 7);
            int r   = idx >> 3;
            int c   = (idx & 7) << 2;
            float4 w4 = *(const float4*)(Wt + (size_t)r * KK + k0 + c);
            float4 wc;
            wc.x = __uint_as_float(f2tf32(w4.x));
            wc.y = __uint_as_float(f2tf32(w4.y));
            wc.z = __uint_as_float(f2tf32(w4.z));
            wc.w = __uint_as_float(f2tf32(w4.w));
            *(float4*)&Bs[r * PSTRIDE + c] = wc;
        }
        __syncthreads();

#pragma unroll
        for (int kk = 0; kk < 4; kk++) {
            uint32_t a[SETS][4];
#pragma unroll
            for (int st = 0; st < SETS; st++) {
                int rr = row0 + st * 16;
                a[st][0] = __float_as_uint(As[rr * PSTRIDE + kk * 8 + c4]);
                a[st][1] = __float_as_uint(As[(rr + 8) * PSTRIDE + kk * 8 + c4]);
                a[st][2] = __float_as_uint(As[rr * PSTRIDE + kk * 8 + c4 + 4]);
                a[st][3] = __float_as_uint(As[(rr + 8) * PSTRIDE + kk * 8 + c4 + 4]);
            }
#pragma unroll
            for (int nt = 0; nt < 8; nt++) {
                uint32_t b0 = __float_as_uint(Bs[(nt * 8 + g) * PSTRIDE + kk * 8 + c4]);
                uint32_t b1 = __float_as_uint(Bs[(nt * 8 + g) * PSTRIDE + kk * 8 + c4 + 4]);
#pragma unroll
                for (int st = 0; st < SETS; st++)
                    mma_tf32(s[st][nt], a[st], b0, b1);
            }
        }
    }

#pragma unroll
    for (int st = 0; st < SETS; st++) {
#pragma unroll
        for (int half = 0; half < 2; half++) {
            int m = m0 + row0 + st * 16 + half * 8;
            int b = m >> 10;
            int n = m & 1023;
#pragma unroll
            for (int nt = 0; nt < 8; nt++) {
                int e = e0 + nt * 8 + (c4 << 1);
                float v0 = half ? s[st][nt][2] : s[st][nt][0];
                float v1 = half ? s[st][nt][3] : s[st][nt][1];
                if (KIND == 1) {
                    float2 r;
                    r.x = v0 + bo[e];
                    r.y = v1 + bo[e + 1];
                    *(float2*)(out + (size_t)m * DQ + e) = r;
                } else if (e0 < 256) {
                    int h = e >> 5, d = e & 31;
                    float2 r; r.x = v0 * QSCALE; r.y = v1 * QSCALE;
                    *(float2*)(g_q + (((size_t)(b * HH + h) * NN + n) << 5) + d) = r;
                } else if (e0 < 512) {
                    int e2 = e - 256;
                    int h = e2 >> 5, d = e2 & 31;
                    float2 r; r.x = v0; r.y = v1;
                    *(float2*)(g_k + (((size_t)(b * HH + h) * NN + n) << 5) + d) = r;
                } else if (e0 < 768) {
                    int e2 = e - 512;
                    int h = e2 >> 5, d = e2 & 31;
                    float2 r; r.x = v0; r.y = v1;
                    *(float2*)(g_v + (((size_t)(b * HH + h) * NN + n) << 5) + d) = r;
                } else {
                    int e2 = e - 768;
                    float z0 = v0 + bg[e2];
                    float z1 = v1 + bg[e2 + 1];
                    float2 r;
                    r.x = 1.f / (1.f + __expf(-z0));
                    r.y = 1.f / (1.f + __expf(-z1));
                    *(float2*)(g_gate + (size_t)m * DQ + e2) = r;
                }
            }
        }
    }
}

// ---------------- attention: R13 base + FULL-coverage bias L2 prefetch ----------------
// Block = 128 threads (4 warps), 128 query rows; grid (8, 32).
// Per tile, each lane prefetches 2 x 128B lines of the NEXT tile's bias:
// c4 selects the (st, half) row, covering all 32 warp rows x 64 cols exactly.
#define K_STRIDE 36
#define V_STRIDE 40

__global__ __launch_bounds__(128, 2) void attn_mma_kernel(
    const float* __restrict__ bias, const float* __restrict__ mask)
{
    __shared__ float Ks[64 * K_STRIDE];
    __shared__ float Vs[64 * V_STRIDE];

    const int t    = threadIdx.x;
    const int warp = t >> 5;
    const int lane = t & 31;
    const int g    = lane >> 2;
    const int c4   = lane & 3;

    const int bh = blockIdx.y;
    const int b  = bh >> 3;
    const int h  = bh & 7;
    const int i0 = blockIdx.x * 128;
    const int row0 = i0 + warp * 32 + g;   // set st: rows row0+st*16, +8

    const float* qbase = g_q + ((size_t)(bh * NN) << 5);
    uint32_t qa[2][4][4];
#pragma unroll
    for (int st = 0; st < 2; st++) {
        int rr = row0 + st * 16;
#pragma unroll
        for (int kk = 0; kk < 4; kk++) {
            qa[st][kk][0] = f2tf32(qbase[((size_t)rr << 5) + kk * 8 + c4]);
            qa[st][kk][1] = f2tf32(qbase[((size_t)(rr + 8) << 5) + kk * 8 + c4]);
            qa[st][kk][2] = f2tf32(qbase[((size_t)rr << 5) + kk * 8 + c4 + 4]);
            qa[st][kk][3] = f2tf32(qbase[((size_t)(rr + 8) << 5) + kk * 8 + c4 + 4]);
        }
    }

    bool rv[2][2];
#pragma unroll
    for (int st = 0; st < 2; st++) {
        rv[st][0] = mask[b * NN + row0 + st * 16] > 0.f;
        rv[st][1] = mask[b * NN + row0 + st * 16 + 8] > 0.f;
    }

    const float* Kg = g_k + ((size_t)bh << 15);
    const float* Vg = g_v + ((size_t)bh << 15);
    const float* biasb = bias + ((size_t)(bh * NN + row0) << 10);
    const float* mrow  = mask + b * NN;

    float lacc[2][2];
    lacc[0][0] = lacc[0][1] = lacc[1][0] = lacc[1][1] = 0.f;
    float o[2][4][4];
#pragma unroll
    for (int st = 0; st < 2; st++)
#pragma unroll
        for (int nt = 0; nt < 4; nt++)
#pragma unroll
            for (int r = 0; r < 4; r++) o[st][nt][r] = 0.f;

    const int lA = (lane & 28) | (c4 >> 1);
    const int lB = lA | 2;
    const bool odd = (lane & 1);
    // prefetch row selector: c4 -> st*16 + half*8 (0, 8, 16, 24)
    const int pfrow = ((c4 >> 1) * 16 + (c4 & 1) * 8);

    for (int j0 = 0; j0 < NN; j0 += 64) {
        __syncthreads();
        // cooperative K/V tile load, tf32 cvt at store
#pragma unroll
        for (int q = 0; q < 4; q++) {
            int id = t + (q << 7);
            int r  = id >> 3;
            int dc = (id & 7) << 2;
            float4 kf = *(const float4*)(Kg + ((size_t)(j0 + r) << 5) + dc);
            float4 vf = *(const float4*)(Vg + ((size_t)(j0 + r) << 5) + dc);
            float4 kc, vc;
            kc.x = __uint_as_float(f2tf32(kf.x));
            kc.y = __uint_as_float(f2tf32(kf.y));
            kc.z = __uint_as_float(f2tf32(kf.z));
            kc.w = __uint_as_float(f2tf32(kf.w));
            vc.x = __uint_as_float(f2tf32(vf.x));
            vc.y = __uint_as_float(f2tf32(vf.y));
            vc.z = __uint_as_float(f2tf32(vf.z));
            vc.w = __uint_as_float(f2tf32(vf.w));
            *(float4*)&Ks[r * K_STRIDE + dc] = kc;
            *(float4*)&Vs[r * V_STRIDE + dc] = vc;
        }
        __syncthreads();

        // FULL-coverage L2 prefetch of next tile's bias: 64 lines/warp = whole tile
        if (j0 + 64 < NN) {
            const float* pb = biasb + ((size_t)pfrow << 10) + (j0 + 64);
            l2_prefetch(pb);
            l2_prefetch(pb + 32);
        }

        // ---- S = Q K^T : B-fragments shared across both row sets ----
        float s[2][8][4];
#pragma unroll
        for (int st = 0; st < 2; st++)
#pragma unroll
            for (int nt = 0; nt < 8; nt++)
                s[st][nt][0] = s[st][nt][1] = s[st][nt][2] = s[st][nt][3] = 0.f;
#pragma unroll
        for (int nt = 0; nt < 8; nt++) {
#pragma unroll
            for (int kk = 0; kk < 4; kk++) {
                uint32_t b0 = __float_as_uint(Ks[(nt * 8 + g) * K_STRIDE + kk * 8 + c4]);
                uint32_t b1 = __float_as_uint(Ks[(nt * 8 + g) * K_STRIDE + kk * 8 + c4 + 4]);
                mma_tf32(s[0][nt], qa[0][kk], b0, b1);
                mma_tf32(s[1][nt], qa[1][kk], b0, b1);
            }
        }

        // ---- bias + mask (branchless selects on exp INPUT) ----
#pragma unroll
        for (int nt = 0; nt < 8; nt++) {
            int jc = j0 + nt * 8 + (c4 << 1);
            float2 mk = *(const float2*)(mrow + jc);
            bool cx = mk.x > 0.f, cy = mk.y > 0.f;
#pragma unroll
            for (int st = 0; st < 2; st++) {
                float2 bz0 = *(const float2*)(biasb + ((size_t)(st * 16) << 10) + jc);
                float2 bz1 = *(const float2*)(biasb + ((size_t)(st * 16 + 8) << 10) + jc);
                s[st][nt][0] = (rv[st][0] && cx) ? s[st][nt][0] + bz0.x : -1e30f;
                s[st][nt][1] = (rv[st][0] && cy) ? s[st][nt][1] + bz0.y : -1e30f;
                s[st][nt][2] = (rv[st][1] && cx) ? s[st][nt][2] + bz1.x : -1e30f;
                s[st][nt][3] = (rv[st][1] && cy) ? s[st][nt][3] + bz1.y : -1e30f;
            }
        }

        // ---- p = exp(s), unconditional; lane-local l ----
#pragma unroll
        for (int st = 0; st < 2; st++) {
#pragma unroll
            for (int nt = 0; nt < 8; nt++) {
                float p0 = __expf(s[st][nt][0]);
                float p1 = __expf(s[st][nt][1]);
                float p2 = __expf(s[st][nt][2]);
                float p3 = __expf(s[st][nt][3]);
                lacc[st][0] += p0 + p1;
                lacc[st][1] += p2 + p3;
                s[st][nt][0] = __uint_as_float(f2tf32(p0));
                s[st][nt][1] = __uint_as_float(f2tf32(p1));
                s[st][nt][2] = __uint_as_float(f2tf32(p2));
                s[st][nt][3] = __uint_as_float(f2tf32(p3));
            }
        }

        // ---- O += P V  (V B-fragments shared across sets) ----
#pragma unroll
        for (int kk = 0; kk < 8; kk++) {
            uint32_t a[2][4];
#pragma unroll
            for (int st = 0; st < 2; st++) {
#pragma unroll
                for (int hv = 0; hv < 2; hv++) {
                    int src = hv ? lB : lA;
                    float w0 = __shfl_sync(0xffffffffu, s[st][kk][0], src);
                    float w1 = __shfl_sync(0xffffffffu, s[st][kk][1], src);
                    float w2 = __shfl_sync(0xffffffffu, s[st][kk][2], src);
                    float w3 = __shfl_sync(0xffffffffu, s[st][kk][3], src);
                    a[st][hv * 2 + 0] = __float_as_uint(odd ? w1 : w0);
                    a[st][hv * 2 + 1] = __float_as_uint(odd ? w3 : w2);
                }
            }
#pragma unroll
            for (int nt = 0; nt < 4; nt++) {
                uint32_t b0 = __float_as_uint(Vs[(kk * 8 + c4) * V_STRIDE + nt * 8 + g]);
                uint32_t b1 = __float_as_uint(Vs[(kk * 8 + c4 + 4) * V_STRIDE + nt * 8 + g]);
                mma_tf32(o[0][nt], a[0], b0, b1);
                mma_tf32(o[1][nt], a[1], b0, b1);
            }
        }
    }

    // ---- single cross-lane l reduction + epilogue ----
#pragma unroll
    for (int st = 0; st < 2; st++) {
        float l0 = lacc[st][0], l1 = lacc[st][1];
        l0 += __shfl_xor_sync(0xffffffffu, l0, 1);
        l0 += __shfl_xor_sync(0xffffffffu, l0, 2);
        l1 += __shfl_xor_sync(0xffffffffu, l1, 1);
        l1 += __shfl_xor_sync(0xffffffffu, l1, 2);
        float inv0 = 1.f / l0, inv1 = 1.f / l1;
        size_t mr0 = (size_t)(b * NN + row0 + st * 16) * DQ + h * 32;
        size_t mr1 = mr0 + (size_t)8 * DQ;
#pragma unroll
        for (int nt = 0; nt < 4; nt++) {
            int dc = nt * 8 + (c4 << 1);
            float2 gt0 = *(const float2*)(g_gate + mr0 + dc);
            float2 gt1 = *(const float2*)(g_gate + mr1 + dc);
            float2 r0, r1;
            r0.x = o[st][nt][0] * inv0 * gt0.x;
            r0.y = o[st][nt][1] * inv0 * gt0.y;
            r1.x = o[st][nt][2] * inv1 * gt1.x;
            r1.y = o[st][nt][3] * inv1 * gt1.y;
            *(float2*)(g_t + mr0 + dc) = r0;
            *(float2*)(g_t + mr1 + dc) = r1;
        }
    }
}

extern "C" void kernel_launch(void* const* d_in, const int* in_sizes, int n_in,
                              void* d_out, int out_size)
{
    const float* x    = (const float*)d_in[0];
    const float* mask = (const float*)d_in[1];
    const float* bias = (const float*)d_in[2];
    const float* Wq   = (const float*)d_in[3];
    const float* Wkv  = (const float*)d_in[4];
    const float* Wo   = (const float*)d_in[5];
    const float* bo   = (const float*)d_in[6];
    const float* Wg   = (const float*)d_in[7];
    const float* bg   = (const float*)d_in[8];
    float* out = (float*)d_out;

    dim3 blk(128);
    // Fused Q + KV + Gate projections (virtual E = 1024), m-tile 128
    proj_kernel<0, 2><<<dim3(16, 32), blk>>>(x, Wq, Wkv, Wg, bg, nullptr, nullptr);
    // Attention (+ gating): R13 config + full bias prefetch
    attn_mma_kernel<<<dim3(NN / 128, BB * HH), blk>>>(bias, mask);
    // Output projection (A = g_t, W = Wo in the Wq slot), m-tile 64
    proj_kernel<1, 1><<<dim3(4, 64), blk>>>(nullptr, Wo, nullptr, nullptr, nullptr, bo, out);
}